// round 2
// baseline (speedup 1.0000x reference)
#include <cuda_runtime.h>
#include <cuda_bf16.h>
#include <math_constants.h>

#define NN 10000
#define EE 320000
#define HD 256      // heads*dim
#define QK 1024     // q|k|v|skip packed width

// ---------------- scratch (device globals; no allocation allowed) ----------------
__device__ float g_Wp1[256 * QK];
__device__ float g_bp1[QK];
__device__ float g_Wp2[256 * QK];
__device__ float g_bp2[QK];
__device__ float g_qkvs[(size_t)NN * QK];     // 40 MB
__device__ float g_h1[(size_t)NN * HD];       // 10 MB
__device__ float g_h2[(size_t)NN * HD];       // 10 MB
__device__ float g_alpha[(size_t)EE * 8];     // 10 MB
__device__ float g_m[NN * 8];
__device__ float g_denom[NN * 8];
__device__ float g_out[(size_t)NN * HD];      // 10 MB
__device__ int   g_srcdst[2 * EE];            // int32 edge index
__device__ int   g_is64;

// ---------------- edge index dtype detect + convert ----------------
__global__ void detect_kernel(const void* ei) {
    if (blockIdx.x == 0 && threadIdx.x == 0) {
        const int* w = (const int*)ei;
        int all_zero = 1;
        for (int i = 0; i < 32; i++) {
            if (w[2 * i + 1] != 0) { all_zero = 0; break; }
        }
        g_is64 = all_zero;  // int64 little-endian -> odd words are high halves == 0
    }
}

__global__ void convert_kernel(const void* ei) {
    int i = blockIdx.x * blockDim.x + threadIdx.x;
    if (i >= 2 * EE) return;
    if (g_is64)
        g_srcdst[i] = (int)((const long long*)ei)[i];
    else
        g_srcdst[i] = ((const int*)ei)[i];
}

// ---------------- weight packing: W = [Wq|Wk|Wv|Wskip] (256 x 1024) ----------------
__global__ void pack_kernel(const float* __restrict__ Wq, const float* __restrict__ bq,
                            const float* __restrict__ Wk, const float* __restrict__ bk,
                            const float* __restrict__ Wv, const float* __restrict__ bv,
                            const float* __restrict__ Ws, const float* __restrict__ bs,
                            float* __restrict__ Wp, float* __restrict__ bp) {
    int i = blockIdx.x * blockDim.x + threadIdx.x;
    if (i >= 256 * QK) return;
    int r = i >> 10, c = i & 1023;
    const float* W; const float* b; int cc;
    if (c < 256)      { W = Wq; b = bq; cc = c; }
    else if (c < 512) { W = Wk; b = bk; cc = c - 256; }
    else if (c < 768) { W = Wv; b = bv; cc = c - 512; }
    else              { W = Ws; b = bs; cc = c - 768; }
    Wp[i] = W[r * 256 + cc];
    if (r == 0) bp[c] = b[cc];
}

// ---------------- GEMM: C[N,1024] = X[N,256] @ Wp[256,1024] + bp ----------------
// 128x128 tile, BK=8, 256 threads, 8x8 per-thread microtile (FFMA-bound ratio).
__global__ __launch_bounds__(256, 2)
void gemm_qkvs(const float* __restrict__ X, const float* __restrict__ Wp,
               const float* __restrict__ bp, float* __restrict__ C) {
    __shared__ float As[8][128];
    __shared__ float Bs[8][128];
    int tid = threadIdx.x;
    int tx = tid & 15, ty = tid >> 4;     // 16x16 thread grid
    int rowBase = blockIdx.y * 128;
    int colBase = blockIdx.x * 128;
    float acc[8][8] = {};

    int am = tid >> 1, ak = (tid & 1) * 4;   // A load: one float4 per thread
    int bk = tid >> 5, bn = (tid & 31) * 4;  // B load: one float4 per thread

    for (int k0 = 0; k0 < 256; k0 += 8) {
        float4 av = make_float4(0.f, 0.f, 0.f, 0.f);
        int arow = rowBase + am;
        if (arow < NN) av = *(const float4*)(X + (size_t)arow * 256 + k0 + ak);
        As[ak + 0][am] = av.x; As[ak + 1][am] = av.y;
        As[ak + 2][am] = av.z; As[ak + 3][am] = av.w;
        *(float4*)(&Bs[bk][bn]) =
            *(const float4*)(Wp + (size_t)(k0 + bk) * QK + colBase + bn);
        __syncthreads();
#pragma unroll
        for (int kk = 0; kk < 8; kk++) {
            float a[8], b[8];
            *(float4*)(a)     = *(const float4*)(&As[kk][ty * 8]);
            *(float4*)(a + 4) = *(const float4*)(&As[kk][ty * 8 + 4]);
            *(float4*)(b)     = *(const float4*)(&Bs[kk][tx * 8]);
            *(float4*)(b + 4) = *(const float4*)(&Bs[kk][tx * 8 + 4]);
#pragma unroll
            for (int i = 0; i < 8; i++)
#pragma unroll
                for (int j = 0; j < 8; j++) acc[i][j] += a[i] * b[j];
        }
        __syncthreads();
    }
#pragma unroll
    for (int i = 0; i < 8; i++) {
        int row = rowBase + ty * 8 + i;
        if (row >= NN) break;
#pragma unroll
        for (int j4 = 0; j4 < 8; j4 += 4) {
            int col = colBase + tx * 8 + j4;
            float4 bb = *(const float4*)(bp + col);
            float4 o = make_float4(acc[i][j4 + 0] + bb.x, acc[i][j4 + 1] + bb.y,
                                   acc[i][j4 + 2] + bb.z, acc[i][j4 + 3] + bb.w);
            *(float4*)(C + (size_t)row * QK + col) = o;
        }
    }
}

// ---------------- init per-layer accumulators ----------------
__global__ void init_md(void) {
    int i = blockIdx.x * blockDim.x + threadIdx.x;
    if (i < NN * HD) g_out[i] = 0.f;
    if (i < NN * 8) { g_m[i] = -CUDART_INF_F; g_denom[i] = 0.f; }
}

__device__ __forceinline__ void atomicMaxF(float* addr, float v) {
    if (v >= 0.f) atomicMax((int*)addr, __float_as_int(v));
    else          atomicMin((unsigned int*)addr, __float_as_uint(v));
}

// ---------------- pass 1: alpha per (edge, head) + segment max ----------------
__global__ void edge_alpha(const float* __restrict__ ew, const float* __restrict__ We) {
    int idx = blockIdx.x * blockDim.x + threadIdx.x;
    if (idx >= EE * 8) return;
    int e = idx >> 3, h = idx & 7;
    int s = g_srcdst[e];
    int d = g_srcdst[EE + e];
    float w = ew[e];
    const float4* q4  = (const float4*)(g_qkvs + (size_t)d * QK + h * 32);
    const float4* k4  = (const float4*)(g_qkvs + (size_t)s * QK + 256 + h * 32);
    const float4* We4 = (const float4*)(We + h * 32);
    float acc = 0.f;
#pragma unroll
    for (int i = 0; i < 8; i++) {
        float4 q = q4[i], k = k4[i], ee = We4[i];
        acc += q.x * fmaf(w, ee.x, k.x);
        acc += q.y * fmaf(w, ee.y, k.y);
        acc += q.z * fmaf(w, ee.z, k.z);
        acc += q.w * fmaf(w, ee.w, k.w);
    }
    acc *= 0.17677669529663687f;  // 1/sqrt(32)
    g_alpha[idx] = acc;
    atomicMaxF(&g_m[d * 8 + h], acc);
}

// ---------------- pass 2: exp, denom, weighted-v scatter ----------------
__global__ void edge_accum(const float* __restrict__ ew, const float* __restrict__ We) {
    int idx = blockIdx.x * blockDim.x + threadIdx.x;
    if (idx >= EE * 8) return;
    int e = idx >> 3, h = idx & 7;
    int s = g_srcdst[e];
    int d = g_srcdst[EE + e];
    float w = ew[e];
    float a = g_alpha[idx];
    float mm = g_m[d * 8 + h];
    float ex = __expf(a - mm);
    atomicAdd(&g_denom[d * 8 + h], ex);
    const float4* v4  = (const float4*)(g_qkvs + (size_t)s * QK + 512 + h * 32);
    const float4* We4 = (const float4*)(We + h * 32);
    float* ob = g_out + (size_t)d * HD + h * 32;
#pragma unroll
    for (int i = 0; i < 8; i++) {
        float4 v = v4[i], ee = We4[i];
        float x0 = ex * fmaf(w, ee.x, v.x);
        float x1 = ex * fmaf(w, ee.y, v.y);
        float x2 = ex * fmaf(w, ee.z, v.z);
        float x3 = ex * fmaf(w, ee.w, v.w);
        asm volatile("red.global.add.v4.f32 [%0], {%1,%2,%3,%4};"
                     :: "l"(ob + i * 4), "f"(x0), "f"(x1), "f"(x2), "f"(x3)
                     : "memory");
    }
}

// ---------------- finalize: normalize, gated skip (one warp per node) ----------------
__global__ void finalize(const float* __restrict__ Wb, float* __restrict__ hout) {
    int gt = blockIdx.x * blockDim.x + threadIdx.x;
    int node = gt >> 5;
    int lane = gt & 31;
    if (node >= NN) return;
    const float* xr = g_qkvs + (size_t)node * QK + 768;
    const float* oa = g_out + (size_t)node * HD;
    float o[8], x[8];
    float dot = 0.f;
#pragma unroll
    for (int j = 0; j < 8; j++) {
        int c = j * 32 + lane;
        float dn = g_denom[node * 8 + j];
        float ov = oa[c] / (dn + 1e-16f);
        float xv = xr[c];
        o[j] = ov; x[j] = xv;
        dot += ov * Wb[c] + xv * Wb[256 + c] + (ov - xv) * Wb[512 + c];
    }
#pragma unroll
    for (int off = 16; off; off >>= 1)
        dot += __shfl_xor_sync(0xffffffffu, dot, off);
    float beta = 1.f / (1.f + __expf(-dot));
#pragma unroll
    for (int j = 0; j < 8; j++)
        hout[(size_t)node * HD + j * 32 + lane] = beta * x[j] + (1.f - beta) * o[j];
}

// ---------------- host orchestration ----------------
static void run_layer(const float* xin, const float* Wp, const float* bp,
                      const float* We, const float* Wb, const float* ew,
                      float* hout) {
    dim3 gg(QK / 128, (NN + 127) / 128);
    float* qkvs; cudaGetSymbolAddress((void**)&qkvs, g_qkvs);
    gemm_qkvs<<<gg, 256>>>(xin, Wp, bp, qkvs);
    init_md<<<(NN * HD + 255) / 256, 256>>>();
    int EH = EE * 8;
    edge_alpha<<<(EH + 255) / 256, 256>>>(ew, We);
    edge_accum<<<(EH + 255) / 256, 256>>>(ew, We);
    finalize<<<(NN * 32 + 127) / 128, 128>>>(Wb, hout);
}

extern "C" void kernel_launch(void* const* d_in, const int* in_sizes, int n_in,
                              void* d_out, int out_size) {
    const float* x  = (const float*)d_in[0];
    const void*  ei = d_in[1];
    const float* ew = (const float*)d_in[2];
    const float* Wq1 = (const float*)d_in[3];  const float* bq1 = (const float*)d_in[4];
    const float* Wk1 = (const float*)d_in[5];  const float* bk1 = (const float*)d_in[6];
    const float* Wv1 = (const float*)d_in[7];  const float* bv1 = (const float*)d_in[8];
    const float* We1 = (const float*)d_in[9];
    const float* Ws1 = (const float*)d_in[10]; const float* bs1 = (const float*)d_in[11];
    const float* Wb1 = (const float*)d_in[12];
    const float* Wq2 = (const float*)d_in[13]; const float* bq2 = (const float*)d_in[14];
    const float* Wk2 = (const float*)d_in[15]; const float* bk2 = (const float*)d_in[16];
    const float* Wv2 = (const float*)d_in[17]; const float* bv2 = (const float*)d_in[18];
    const float* We2 = (const float*)d_in[19];
    const float* Ws2 = (const float*)d_in[20]; const float* bs2 = (const float*)d_in[21];
    const float* Wb2 = (const float*)d_in[22];

    float *Wp1, *bp1, *Wp2, *bp2, *h1, *h2;
    cudaGetSymbolAddress((void**)&Wp1, g_Wp1);
    cudaGetSymbolAddress((void**)&bp1, g_bp1);
    cudaGetSymbolAddress((void**)&Wp2, g_Wp2);
    cudaGetSymbolAddress((void**)&bp2, g_bp2);
    cudaGetSymbolAddress((void**)&h1, g_h1);
    cudaGetSymbolAddress((void**)&h2, g_h2);

    // edge index dtype detect + int32 conversion
    detect_kernel<<<1, 32>>>(ei);
    convert_kernel<<<(2 * EE + 255) / 256, 256>>>(ei);

    // pack fused weights for both parameter sets
    pack_kernel<<<(256 * QK + 255) / 256, 256>>>(Wq1, bq1, Wk1, bk1, Wv1, bv1, Ws1, bs1, Wp1, bp1);
    pack_kernel<<<(256 * QK + 255) / 256, 256>>>(Wq2, bq2, Wk2, bk2, Wv2, bv2, Ws2, bs2, Wp2, bp2);

    // 3 conv layers (layer 1 uses p1; layers 2 and 3 use p2)
    run_layer(x,  Wp1, bp1, We1, Wb1, ew, h1);
    run_layer(h1, Wp2, bp2, We2, Wb2, ew, h2);
    run_layer(h2, Wp2, bp2, We2, Wb2, ew, (float*)d_out);
}

// round 3
// speedup vs baseline: 1.2020x; 1.2020x over previous
#include <cuda_runtime.h>
#include <cuda_bf16.h>
#include <math_constants.h>

#define NN 10000
#define EE 320000
#define HD 256      // heads*dim
#define QK 1024     // q|k|v|skip packed width

// ---------------- scratch (device globals; no allocation allowed) ----------------
__device__ float g_Wp1[256 * QK];
__device__ float g_bp1[QK];
__device__ float g_Wp2[256 * QK];
__device__ float g_bp2[QK];
__device__ float g_Wqe1[256 * 8];
__device__ float g_bqe1[8];
__device__ float g_Wqe2[256 * 8];
__device__ float g_bqe2[8];
__device__ float g_qkvs[(size_t)NN * QK];     // 40 MB
__device__ float g_h1[(size_t)NN * HD];       // 10 MB
__device__ float g_h2[(size_t)NN * HD];       // 10 MB
__device__ float g_qwe[NN * 8];               // per-node per-head q.We
__device__ float2 g_dc[NN * 8];               // (denom, coeff) accumulators
__device__ float g_out[(size_t)NN * HD];      // 10 MB
__device__ int   g_srcdst[2 * EE];            // int32 edge index
__device__ int   g_is64;

// ---------------- edge index dtype detect + convert ----------------
__global__ void detect_kernel(const void* ei) {
    if (blockIdx.x == 0 && threadIdx.x == 0) {
        const int* w = (const int*)ei;
        int all_zero = 1;
        for (int i = 0; i < 32; i++) {
            if (w[2 * i + 1] != 0) { all_zero = 0; break; }
        }
        g_is64 = all_zero;  // int64 little-endian -> odd words are high halves == 0
    }
}

__global__ void convert_kernel(const void* ei) {
    int i = blockIdx.x * blockDim.x + threadIdx.x;
    if (i >= 2 * EE) return;
    if (g_is64)
        g_srcdst[i] = (int)((const long long*)ei)[i];
    else
        g_srcdst[i] = ((const int*)ei)[i];
}

// ---------------- weight packing: W = [Wq|Wk|Wv|Wskip], plus Wqe = Wq folded with We ----------------
__global__ void pack_kernel(const float* __restrict__ Wq, const float* __restrict__ bq,
                            const float* __restrict__ Wk, const float* __restrict__ bk,
                            const float* __restrict__ Wv, const float* __restrict__ bv,
                            const float* __restrict__ Ws, const float* __restrict__ bs,
                            const float* __restrict__ We,
                            float* __restrict__ Wp, float* __restrict__ bp,
                            float* __restrict__ Wqe, float* __restrict__ bqe) {
    int i = blockIdx.x * blockDim.x + threadIdx.x;
    if (i >= 256 * QK) return;
    int r = i >> 10, c = i & 1023;
    const float* W; const float* b; int cc;
    if (c < 256)      { W = Wq; b = bq; cc = c; }
    else if (c < 512) { W = Wk; b = bk; cc = c - 256; }
    else if (c < 768) { W = Wv; b = bv; cc = c - 512; }
    else              { W = Ws; b = bs; cc = c - 768; }
    Wp[i] = W[r * 256 + cc];
    if (r == 0) bp[c] = b[cc];
    // Wqe[r][h] = sum_t Wq[r, h*32+t] * We[h*32+t]
    if (i < 2048) {
        int rr = i >> 3, h = i & 7;
        float s = 0.f;
#pragma unroll
        for (int t = 0; t < 32; t++) s += Wq[rr * 256 + h * 32 + t] * We[h * 32 + t];
        Wqe[rr * 8 + h] = s;
    }
    if (i < 8) {
        float s = 0.f;
#pragma unroll
        for (int t = 0; t < 32; t++) s += bq[i * 32 + t] * We[i * 32 + t];
        bqe[i] = s;
    }
}

// ---------------- per-node q.We: qwe[n,h] = x[n,:] @ Wqe[:,h] + bqe[h] ----------------
__global__ void qwe_kernel(const float* __restrict__ x, const float* __restrict__ Wqe,
                           const float* __restrict__ bqe) {
    int gt = blockIdx.x * blockDim.x + threadIdx.x;
    int node = gt >> 5, lane = gt & 31;
    if (node >= NN) return;
    float xv[8];
#pragma unroll
    for (int j = 0; j < 8; j++) xv[j] = x[(size_t)node * 256 + j * 32 + lane];
    float p[8];
#pragma unroll
    for (int h = 0; h < 8; h++) {
        float s = 0.f;
#pragma unroll
        for (int j = 0; j < 8; j++) s += xv[j] * Wqe[(j * 32 + lane) * 8 + h];
#pragma unroll
        for (int off = 16; off; off >>= 1) s += __shfl_xor_sync(0xffffffffu, s, off);
        p[h] = s;
    }
    if (lane < 8) g_qwe[node * 8 + lane] = p[lane] + bqe[lane];
}

// ---------------- GEMM: C[N,1024] = X[N,256] @ Wp[256,1024] + bp ----------------
// 128x128 tile, BK=8, 256 threads, 8x8 microtile. Epilogue zeroes g_out/g_dc.
__global__ __launch_bounds__(256, 2)
void gemm_qkvs(const float* __restrict__ X, const float* __restrict__ Wp,
               const float* __restrict__ bp, float* __restrict__ C) {
    __shared__ float As[8][128];
    __shared__ float Bs[8][128];
    int tid = threadIdx.x;
    int tx = tid & 15, ty = tid >> 4;
    int rowBase = blockIdx.y * 128;
    int colBase = blockIdx.x * 128;
    float acc[8][8] = {};

    int am = tid >> 1, ak = (tid & 1) * 4;
    int bk = tid >> 5, bn = (tid & 31) * 4;

    for (int k0 = 0; k0 < 256; k0 += 8) {
        float4 av = make_float4(0.f, 0.f, 0.f, 0.f);
        int arow = rowBase + am;
        if (arow < NN) av = *(const float4*)(X + (size_t)arow * 256 + k0 + ak);
        As[ak + 0][am] = av.x; As[ak + 1][am] = av.y;
        As[ak + 2][am] = av.z; As[ak + 3][am] = av.w;
        *(float4*)(&Bs[bk][bn]) =
            *(const float4*)(Wp + (size_t)(k0 + bk) * QK + colBase + bn);
        __syncthreads();
#pragma unroll
        for (int kk = 0; kk < 8; kk++) {
            float a[8], b[8];
            *(float4*)(a)     = *(const float4*)(&As[kk][ty * 8]);
            *(float4*)(a + 4) = *(const float4*)(&As[kk][ty * 8 + 4]);
            *(float4*)(b)     = *(const float4*)(&Bs[kk][tx * 8]);
            *(float4*)(b + 4) = *(const float4*)(&Bs[kk][tx * 8 + 4]);
#pragma unroll
            for (int i = 0; i < 8; i++)
#pragma unroll
                for (int j = 0; j < 8; j++) acc[i][j] += a[i] * b[j];
        }
        __syncthreads();
    }
#pragma unroll
    for (int i = 0; i < 8; i++) {
        int row = rowBase + ty * 8 + i;
        if (row >= NN) break;
#pragma unroll
        for (int j4 = 0; j4 < 8; j4 += 4) {
            int col = colBase + tx * 8 + j4;
            float4 bb = *(const float4*)(bp + col);
            float4 o = make_float4(acc[i][j4 + 0] + bb.x, acc[i][j4 + 1] + bb.y,
                                   acc[i][j4 + 2] + bb.z, acc[i][j4 + 3] + bb.w);
            *(float4*)(C + (size_t)row * QK + col) = o;
        }
    }
    // epilogue: zero per-layer accumulators (g_out: 640000 f4, g_dc: 40000 f4)
    {
        int nthreads = gridDim.x * gridDim.y * 256;
        int flat = (blockIdx.y * gridDim.x + blockIdx.x) * 256 + tid;
        float4 z = make_float4(0.f, 0.f, 0.f, 0.f);
        for (int i = flat; i < 640000; i += nthreads)
            ((float4*)g_out)[i] = z;
        for (int i = flat; i < 40000; i += nthreads)
            ((float4*)g_dc)[i] = z;
    }
}

// ---------------- single-pass edge softmax-accumulate (no max subtraction) ----------------
__global__ void edge_soft(const float* __restrict__ ew, const float* __restrict__ qwe) {
    int idx = blockIdx.x * blockDim.x + threadIdx.x;
    if (idx >= EE * 8) return;
    int e = idx >> 3, h = idx & 7;
    int s = g_srcdst[e];
    int d = g_srcdst[EE + e];
    float w = ew[e];
    const float4* q4 = (const float4*)(g_qkvs + (size_t)d * QK + h * 32);
    const float4* k4 = (const float4*)(g_qkvs + (size_t)s * QK + 256 + h * 32);
    float dot = 0.f;
#pragma unroll
    for (int i = 0; i < 8; i++) {
        float4 q = q4[i], k = k4[i];
        dot += q.x * k.x + q.y * k.y + q.z * k.z + q.w * k.w;
    }
    float alpha = (dot + w * qwe[d * 8 + h]) * 0.17677669529663687f;  // 1/sqrt(32)
    float ex = __expf(alpha);
    float exw = ex * w;
    asm volatile("red.global.add.v2.f32 [%0], {%1,%2};"
                 :: "l"(&g_dc[d * 8 + h]), "f"(ex), "f"(exw) : "memory");
    const float4* v4 = (const float4*)(g_qkvs + (size_t)s * QK + 512 + h * 32);
    float* ob = g_out + (size_t)d * HD + h * 32;
#pragma unroll
    for (int i = 0; i < 8; i++) {
        float4 v = v4[i];
        asm volatile("red.global.add.v4.f32 [%0], {%1,%2,%3,%4};"
                     :: "l"(ob + i * 4), "f"(ex * v.x), "f"(ex * v.y),
                        "f"(ex * v.z), "f"(ex * v.w) : "memory");
    }
}

// ---------------- finalize: normalize (+ coeff*We), gated skip (one warp per node) ----------------
__global__ void finalize(const float* __restrict__ Wb, const float* __restrict__ We,
                         float* __restrict__ hout) {
    int gt = blockIdx.x * blockDim.x + threadIdx.x;
    int node = gt >> 5;
    int lane = gt & 31;
    if (node >= NN) return;
    const float* xr = g_qkvs + (size_t)node * QK + 768;
    const float* oa = g_out + (size_t)node * HD;
    float o[8], x[8];
    float dot = 0.f;
#pragma unroll
    for (int j = 0; j < 8; j++) {
        int c = j * 32 + lane;
        float2 dc = g_dc[node * 8 + j];
        float ov = (oa[c] + dc.y * We[c]) / (dc.x + 1e-16f);
        float xv = xr[c];
        o[j] = ov; x[j] = xv;
        dot += ov * Wb[c] + xv * Wb[256 + c] + (ov - xv) * Wb[512 + c];
    }
#pragma unroll
    for (int off = 16; off; off >>= 1)
        dot += __shfl_xor_sync(0xffffffffu, dot, off);
    float beta = 1.f / (1.f + __expf(-dot));
#pragma unroll
    for (int j = 0; j < 8; j++)
        hout[(size_t)node * HD + j * 32 + lane] = beta * x[j] + (1.f - beta) * o[j];
}

// ---------------- host orchestration ----------------
static void run_layer(const float* xin, const float* Wp, const float* bp,
                      const float* Wqe, const float* bqe,
                      const float* We, const float* Wb, const float* ew,
                      float* hout) {
    float* qkvs; cudaGetSymbolAddress((void**)&qkvs, g_qkvs);
    float* qwe;  cudaGetSymbolAddress((void**)&qwe, g_qwe);
    qwe_kernel<<<(NN * 32 + 255) / 256, 256>>>(xin, Wqe, bqe);
    dim3 gg(QK / 128, (NN + 127) / 128);
    gemm_qkvs<<<gg, 256>>>(xin, Wp, bp, qkvs);
    int EH = EE * 8;
    edge_soft<<<(EH + 255) / 256, 256>>>(ew, qwe);
    finalize<<<(NN * 32 + 127) / 128, 128>>>(Wb, We, hout);
}

extern "C" void kernel_launch(void* const* d_in, const int* in_sizes, int n_in,
                              void* d_out, int out_size) {
    const float* x  = (const float*)d_in[0];
    const void*  ei = d_in[1];
    const float* ew = (const float*)d_in[2];
    const float* Wq1 = (const float*)d_in[3];  const float* bq1 = (const float*)d_in[4];
    const float* Wk1 = (const float*)d_in[5];  const float* bk1 = (const float*)d_in[6];
    const float* Wv1 = (const float*)d_in[7];  const float* bv1 = (const float*)d_in[8];
    const float* We1 = (const float*)d_in[9];
    const float* Ws1 = (const float*)d_in[10]; const float* bs1 = (const float*)d_in[11];
    const float* Wb1 = (const float*)d_in[12];
    const float* Wq2 = (const float*)d_in[13]; const float* bq2 = (const float*)d_in[14];
    const float* Wk2 = (const float*)d_in[15]; const float* bk2 = (const float*)d_in[16];
    const float* Wv2 = (const float*)d_in[17]; const float* bv2 = (const float*)d_in[18];
    const float* We2 = (const float*)d_in[19];
    const float* Ws2 = (const float*)d_in[20]; const float* bs2 = (const float*)d_in[21];
    const float* Wb2 = (const float*)d_in[22];

    float *Wp1, *bp1, *Wp2, *bp2, *Wqe1, *bqe1, *Wqe2, *bqe2, *h1, *h2;
    cudaGetSymbolAddress((void**)&Wp1, g_Wp1);
    cudaGetSymbolAddress((void**)&bp1, g_bp1);
    cudaGetSymbolAddress((void**)&Wp2, g_Wp2);
    cudaGetSymbolAddress((void**)&bp2, g_bp2);
    cudaGetSymbolAddress((void**)&Wqe1, g_Wqe1);
    cudaGetSymbolAddress((void**)&bqe1, g_bqe1);
    cudaGetSymbolAddress((void**)&Wqe2, g_Wqe2);
    cudaGetSymbolAddress((void**)&bqe2, g_bqe2);
    cudaGetSymbolAddress((void**)&h1, g_h1);
    cudaGetSymbolAddress((void**)&h2, g_h2);

    detect_kernel<<<1, 32>>>(ei);
    convert_kernel<<<(2 * EE + 255) / 256, 256>>>(ei);

    pack_kernel<<<(256 * QK + 255) / 256, 256>>>(Wq1, bq1, Wk1, bk1, Wv1, bv1, Ws1, bs1,
                                                 We1, Wp1, bp1, Wqe1, bqe1);
    pack_kernel<<<(256 * QK + 255) / 256, 256>>>(Wq2, bq2, Wk2, bk2, Wv2, bv2, Ws2, bs2,
                                                 We2, Wp2, bp2, Wqe2, bqe2);

    run_layer(x,  Wp1, bp1, Wqe1, bqe1, We1, Wb1, ew, h1);
    run_layer(h1, Wp2, bp2, Wqe2, bqe2, We2, Wb2, ew, h2);
    run_layer(h2, Wp2, bp2, Wqe2, bqe2, We2, Wb2, ew, (float*)d_out);
}

// round 7
// speedup vs baseline: 1.8088x; 1.5048x over previous
#include <cuda_runtime.h>
#include <cuda_bf16.h>
#include <math_constants.h>

#define NN 10000
#define EE 320000
#define HD 256      // heads*dim
#define QK 1024     // q|k|v|skip packed width

// ---------------- scratch (device globals; no allocation allowed) ----------------
__device__ float g_Wp1[256 * QK];
__device__ float g_bp1[QK];
__device__ float g_Wp2[256 * QK];
__device__ float g_bp2[QK];
__device__ float g_Wqe1[256 * 8];
__device__ float g_bqe1[8];
__device__ float g_Wqe2[256 * 8];
__device__ float g_bqe2[8];
__device__ float g_qkvs[(size_t)NN * QK];     // 40 MB
__device__ float g_h1[(size_t)NN * HD];       // 10 MB
__device__ float g_h2[(size_t)NN * HD];       // 10 MB
__device__ float g_qwe[NN * 8];               // per-node per-head q.We
__device__ float2 g_dc[NN * 8];               // (denom, coeff)
__device__ float g_out[(size_t)NN * HD];      // 10 MB
__device__ int   g_srcdst[2 * EE];            // int32 edge index
__device__ int   g_is64;
// CSR by dst
__device__ int   g_cnt[NN];
__device__ int   g_cur[NN];
__device__ int   g_off[NN + 1];
__device__ int   g_esrc[EE];
__device__ float g_eew[EE];

// ---------------- edge index dtype detect + convert ----------------
__global__ void detect_kernel(const void* ei) {
    if (blockIdx.x == 0 && threadIdx.x == 0) {
        const int* w = (const int*)ei;
        int all_zero = 1;
        for (int i = 0; i < 32; i++) {
            if (w[2 * i + 1] != 0) { all_zero = 0; break; }
        }
        g_is64 = all_zero;  // int64 little-endian -> odd words are high halves == 0
    }
}

__global__ void convert_kernel(const void* ei) {
    int i = blockIdx.x * blockDim.x + threadIdx.x;
    if (i >= 2 * EE) return;
    if (g_is64)
        g_srcdst[i] = (int)((const long long*)ei)[i];
    else
        g_srcdst[i] = ((const int*)ei)[i];
}

// ---------------- CSR build ----------------
__global__ void zero_cnt(void) {
    int i = blockIdx.x * blockDim.x + threadIdx.x;
    if (i < NN) g_cnt[i] = 0;
}

__global__ void count_kernel(void) {
    int e = blockIdx.x * blockDim.x + threadIdx.x;
    if (e < EE) atomicAdd(&g_cnt[g_srcdst[EE + e]], 1);
}

// one block, 1024 threads, 10 elems/thread: exclusive scan of g_cnt -> g_off
__global__ void scan_kernel(void) {
    __shared__ int s[1024];
    int t = threadIdx.x;
    int base = t * 10;
    int local[10];
    int sum = 0;
#pragma unroll
    for (int i = 0; i < 10; i++) {
        int idx = base + i;
        int v = (idx < NN) ? g_cnt[idx] : 0;
        local[i] = v; sum += v;
    }
    s[t] = sum;
    __syncthreads();
    for (int off = 1; off < 1024; off <<= 1) {
        int v = (t >= off) ? s[t - off] : 0;
        __syncthreads();
        if (t >= off) s[t] += v;
        __syncthreads();
    }
    int excl = (t == 0) ? 0 : s[t - 1];
#pragma unroll
    for (int i = 0; i < 10; i++) {
        int idx = base + i;
        if (idx < NN) { g_off[idx] = excl; g_cur[idx] = 0; }
        excl += local[i];
    }
    if (t == 1023) g_off[NN] = s[1023];
}

__global__ void scatter_kernel(const float* __restrict__ ew) {
    int e = blockIdx.x * blockDim.x + threadIdx.x;
    if (e >= EE) return;
    int d = g_srcdst[EE + e];
    int pos = g_off[d] + atomicAdd(&g_cur[d], 1);
    g_esrc[pos] = g_srcdst[e];
    g_eew[pos] = ew[e];
}

// ---------------- weight packing: W = [Wq|Wk|Wv|Wskip], plus Wqe = Wq folded with We ----------------
__global__ void pack_kernel(const float* __restrict__ Wq, const float* __restrict__ bq,
                            const float* __restrict__ Wk, const float* __restrict__ bk,
                            const float* __restrict__ Wv, const float* __restrict__ bv,
                            const float* __restrict__ Ws, const float* __restrict__ bs,
                            const float* __restrict__ We,
                            float* __restrict__ Wp, float* __restrict__ bp,
                            float* __restrict__ Wqe, float* __restrict__ bqe) {
    int i = blockIdx.x * blockDim.x + threadIdx.x;
    if (i >= 256 * QK) return;
    int r = i >> 10, c = i & 1023;
    const float* W; const float* b; int cc;
    if (c < 256)      { W = Wq; b = bq; cc = c; }
    else if (c < 512) { W = Wk; b = bk; cc = c - 256; }
    else if (c < 768) { W = Wv; b = bv; cc = c - 512; }
    else              { W = Ws; b = bs; cc = c - 768; }
    Wp[i] = W[r * 256 + cc];
    if (r == 0) bp[c] = b[cc];
    if (i < 2048) {
        int rr = i >> 3, h = i & 7;
        float s = 0.f;
#pragma unroll
        for (int t = 0; t < 32; t++) s += Wq[rr * 256 + h * 32 + t] * We[h * 32 + t];
        Wqe[rr * 8 + h] = s;
    }
    if (i < 8) {
        float s = 0.f;
#pragma unroll
        for (int t = 0; t < 32; t++) s += bq[i * 32 + t] * We[i * 32 + t];
        bqe[i] = s;
    }
}

// ---------------- per-node q.We ----------------
__global__ void qwe_kernel(const float* __restrict__ x, const float* __restrict__ Wqe,
                           const float* __restrict__ bqe) {
    int gt = blockIdx.x * blockDim.x + threadIdx.x;
    int node = gt >> 5, lane = gt & 31;
    if (node >= NN) return;
    float xv[8];
#pragma unroll
    for (int j = 0; j < 8; j++) xv[j] = x[(size_t)node * 256 + j * 32 + lane];
    float p[8];
#pragma unroll
    for (int h = 0; h < 8; h++) {
        float s = 0.f;
#pragma unroll
        for (int j = 0; j < 8; j++) s += xv[j] * Wqe[(j * 32 + lane) * 8 + h];
#pragma unroll
        for (int off = 16; off; off >>= 1) s += __shfl_xor_sync(0xffffffffu, s, off);
        p[h] = s;
    }
    if (lane < 8) g_qwe[node * 8 + lane] = p[lane] + bqe[lane];
}

// ---------------- GEMM: C[N,1024] = X[N,256] @ Wp[256,1024] + bp ----------------
__global__ __launch_bounds__(256, 2)
void gemm_qkvs(const float* __restrict__ X, const float* __restrict__ Wp,
               const float* __restrict__ bp, float* __restrict__ C) {
    __shared__ float As[8][128];
    __shared__ float Bs[8][128];
    int tid = threadIdx.x;
    int tx = tid & 15, ty = tid >> 4;
    int rowBase = blockIdx.y * 128;
    int colBase = blockIdx.x * 128;
    float acc[8][8] = {};

    int am = tid >> 1, ak = (tid & 1) * 4;
    int bk = tid >> 5, bn = (tid & 31) * 4;

    for (int k0 = 0; k0 < 256; k0 += 8) {
        float4 av = make_float4(0.f, 0.f, 0.f, 0.f);
        int arow = rowBase + am;
        if (arow < NN) av = *(const float4*)(X + (size_t)arow * 256 + k0 + ak);
        As[ak + 0][am] = av.x; As[ak + 1][am] = av.y;
        As[ak + 2][am] = av.z; As[ak + 3][am] = av.w;
        *(float4*)(&Bs[bk][bn]) =
            *(const float4*)(Wp + (size_t)(k0 + bk) * QK + colBase + bn);
        __syncthreads();
#pragma unroll
        for (int kk = 0; kk < 8; kk++) {
            float a[8], b[8];
            *(float4*)(a)     = *(const float4*)(&As[kk][ty * 8]);
            *(float4*)(a + 4) = *(const float4*)(&As[kk][ty * 8 + 4]);
            *(float4*)(b)     = *(const float4*)(&Bs[kk][tx * 8]);
            *(float4*)(b + 4) = *(const float4*)(&Bs[kk][tx * 8 + 4]);
#pragma unroll
            for (int i = 0; i < 8; i++)
#pragma unroll
                for (int j = 0; j < 8; j++) acc[i][j] += a[i] * b[j];
        }
        __syncthreads();
    }
#pragma unroll
    for (int i = 0; i < 8; i++) {
        int row = rowBase + ty * 8 + i;
        if (row >= NN) break;
#pragma unroll
        for (int j4 = 0; j4 < 8; j4 += 4) {
            int col = colBase + tx * 8 + j4;
            float4 bb = *(const float4*)(bp + col);
            float4 o = make_float4(acc[i][j4 + 0] + bb.x, acc[i][j4 + 1] + bb.y,
                                   acc[i][j4 + 2] + bb.z, acc[i][j4 + 3] + bb.w);
            *(float4*)(C + (size_t)row * QK + col) = o;
        }
    }
}

// ---------------- CSR gather attention: one warp per (node, head), no atomics ----------------
// Software pipeline depth 2: k/v of edge i+2 in flight while edge i reduces.
__global__ __launch_bounds__(256)
void agg_kernel(const float* __restrict__ qwe) {
    int warpId = (blockIdx.x * blockDim.x + threadIdx.x) >> 5;
    int lane = threadIdx.x & 31;
    if (warpId >= NN * 8) return;
    int node = warpId >> 3, h = warpId & 7;
    float q = g_qkvs[(size_t)node * QK + h * 32 + lane];
    float qw = qwe[node * 8 + h];
    int beg = g_off[node], end = g_off[node + 1];

    float acc = 0.f, denom = 0.f, coeff = 0.f;

    float w0 = 0.f, k0 = 0.f, v0 = 0.f;   // stage: edge i
    float w1 = 0.f, k1 = 0.f, v1 = 0.f;   // stage: edge i+1
    if (beg < end) {
        int s = g_esrc[beg]; w0 = g_eew[beg];
        k0 = g_qkvs[(size_t)s * QK + 256 + h * 32 + lane];
        v0 = g_qkvs[(size_t)s * QK + 512 + h * 32 + lane];
    }
    if (beg + 1 < end) {
        int s = g_esrc[beg + 1]; w1 = g_eew[beg + 1];
        k1 = g_qkvs[(size_t)s * QK + 256 + h * 32 + lane];
        v1 = g_qkvs[(size_t)s * QK + 512 + h * 32 + lane];
    }
    for (int i = beg; i < end; i++) {
        float w2 = 0.f, k2 = 0.f, v2 = 0.f;
        if (i + 2 < end) {
            int s = g_esrc[i + 2]; w2 = g_eew[i + 2];
            k2 = g_qkvs[(size_t)s * QK + 256 + h * 32 + lane];
            v2 = g_qkvs[(size_t)s * QK + 512 + h * 32 + lane];
        }
        float dv = q * k0;
#pragma unroll
        for (int off = 16; off; off >>= 1)
            dv += __shfl_xor_sync(0xffffffffu, dv, off);
        float ex = __expf((dv + w0 * qw) * 0.17677669529663687f);
        denom += ex;
        coeff += ex * w0;
        acc += ex * v0;
        w0 = w1; k0 = k1; v0 = v1;
        w1 = w2; k1 = k2; v1 = v2;
    }
    g_out[(size_t)node * HD + h * 32 + lane] = acc;
    if (lane == 0) g_dc[node * 8 + h] = make_float2(denom, coeff);
}

// ---------------- finalize: normalize (+ coeff*We), gated skip ----------------
__global__ void finalize(const float* __restrict__ Wb, const float* __restrict__ We,
                         float* __restrict__ hout) {
    int gt = blockIdx.x * blockDim.x + threadIdx.x;
    int node = gt >> 5;
    int lane = gt & 31;
    if (node >= NN) return;
    const float* xr = g_qkvs + (size_t)node * QK + 768;
    const float* oa = g_out + (size_t)node * HD;
    float o[8], x[8];
    float dot = 0.f;
#pragma unroll
    for (int j = 0; j < 8; j++) {
        int c = j * 32 + lane;
        float2 dc = g_dc[node * 8 + j];
        float ov = (oa[c] + dc.y * We[c]) / (dc.x + 1e-16f);
        float xv = xr[c];
        o[j] = ov; x[j] = xv;
        dot += ov * Wb[c] + xv * Wb[256 + c] + (ov - xv) * Wb[512 + c];
    }
#pragma unroll
    for (int off = 16; off; off >>= 1)
        dot += __shfl_xor_sync(0xffffffffu, dot, off);
    float beta = 1.f / (1.f + __expf(-dot));
#pragma unroll
    for (int j = 0; j < 8; j++)
        hout[(size_t)node * HD + j * 32 + lane] = beta * x[j] + (1.f - beta) * o[j];
}

// ---------------- host orchestration ----------------
static void run_layer(const float* xin, const float* Wp, const float* bp,
                      const float* Wqe, const float* bqe,
                      const float* We, const float* Wb, const float* ew,
                      float* hout) {
    float* qkvs; cudaGetSymbolAddress((void**)&qkvs, g_qkvs);
    float* qwe;  cudaGetSymbolAddress((void**)&qwe, g_qwe);
    qwe_kernel<<<(NN * 32 + 255) / 256, 256>>>(xin, Wqe, bqe);
    dim3 gg(QK / 128, (NN + 127) / 128);
    gemm_qkvs<<<gg, 256>>>(xin, Wp, bp, qkvs);
    agg_kernel<<<(NN * 8 * 32 + 255) / 256, 256>>>(qwe);
    finalize<<<(NN * 32 + 127) / 128, 128>>>(Wb, We, hout);
}

extern "C" void kernel_launch(void* const* d_in, const int* in_sizes, int n_in,
                              void* d_out, int out_size) {
    const float* x  = (const float*)d_in[0];
    const void*  ei = d_in[1];
    const float* ew = (const float*)d_in[2];
    const float* Wq1 = (const float*)d_in[3];  const float* bq1 = (const float*)d_in[4];
    const float* Wk1 = (const float*)d_in[5];  const float* bk1 = (const float*)d_in[6];
    const float* Wv1 = (const float*)d_in[7];  const float* bv1 = (const float*)d_in[8];
    const float* We1 = (const float*)d_in[9];
    const float* Ws1 = (const float*)d_in[10]; const float* bs1 = (const float*)d_in[11];
    const float* Wb1 = (const float*)d_in[12];
    const float* Wq2 = (const float*)d_in[13]; const float* bq2 = (const float*)d_in[14];
    const float* Wk2 = (const float*)d_in[15]; const float* bk2 = (const float*)d_in[16];
    const float* Wv2 = (const float*)d_in[17]; const float* bv2 = (const float*)d_in[18];
    const float* We2 = (const float*)d_in[19];
    const float* Ws2 = (const float*)d_in[20]; const float* bs2 = (const float*)d_in[21];
    const float* Wb2 = (const float*)d_in[22];

    float *Wp1, *bp1, *Wp2, *bp2, *Wqe1, *bqe1, *Wqe2, *bqe2, *h1, *h2;
    cudaGetSymbolAddress((void**)&Wp1, g_Wp1);
    cudaGetSymbolAddress((void**)&bp1, g_bp1);
    cudaGetSymbolAddress((void**)&Wp2, g_Wp2);
    cudaGetSymbolAddress((void**)&bp2, g_bp2);
    cudaGetSymbolAddress((void**)&Wqe1, g_Wqe1);
    cudaGetSymbolAddress((void**)&bqe1, g_bqe1);
    cudaGetSymbolAddress((void**)&Wqe2, g_Wqe2);
    cudaGetSymbolAddress((void**)&bqe2, g_bqe2);
    cudaGetSymbolAddress((void**)&h1, g_h1);
    cudaGetSymbolAddress((void**)&h2, g_h2);

    detect_kernel<<<1, 32>>>(ei);
    convert_kernel<<<(2 * EE + 255) / 256, 256>>>(ei);

    // CSR build (per call; graph-capturable)
    zero_cnt<<<(NN + 255) / 256, 256>>>();
    count_kernel<<<(EE + 255) / 256, 256>>>();
    scan_kernel<<<1, 1024>>>();
    scatter_kernel<<<(EE + 255) / 256, 256>>>(ew);

    pack_kernel<<<(256 * QK + 255) / 256, 256>>>(Wq1, bq1, Wk1, bk1, Wv1, bv1, Ws1, bs1,
                                                 We1, Wp1, bp1, Wqe1, bqe1);
    pack_kernel<<<(256 * QK + 255) / 256, 256>>>(Wq2, bq2, Wk2, bk2, Wv2, bv2, Ws2, bs2,
                                                 We2, Wp2, bp2, Wqe2, bqe2);

    run_layer(x,  Wp1, bp1, Wqe1, bqe1, We1, Wb1, ew, h1);
    run_layer(h1, Wp2, bp2, Wqe2, bqe2, We2, Wb2, ew, h2);
    run_layer(h2, Wp2, bp2, Wqe2, bqe2, We2, Wb2, ew, (float*)d_out);
}

// round 12
// speedup vs baseline: 1.8574x; 1.0269x over previous
#include <cuda_runtime.h>
#include <cuda_bf16.h>
#include <math_constants.h>
#include <cstdint>

#define NN 10000
#define EE 320000
#define HD 256      // heads*dim
#define QK 1024     // q|k|v|skip packed width

// ---------------- scratch (device globals; no allocation allowed) ----------------
__device__ float g_Whi1[256 * QK];    // W hi plane, [k][n] layout
__device__ float g_Wlo1[256 * QK];    // W lo plane (tf32-rounded)
__device__ float g_bp1[QK];
__device__ float g_Whi2[256 * QK];
__device__ float g_Wlo2[256 * QK];
__device__ float g_bp2[QK];
__device__ float g_Wqe1[256 * 8];
__device__ float g_bqe1[8];
__device__ float g_Wqe2[256 * 8];
__device__ float g_bqe2[8];
__device__ float g_Ahi[(size_t)NN * 256];   // x hi plane [m][k]
__device__ float g_Alo[(size_t)NN * 256];   // x lo plane (tf32-rounded)
__device__ float g_qkvs[(size_t)NN * QK];   // 40 MB
__device__ float g_h1[(size_t)NN * HD];
__device__ float g_h2[(size_t)NN * HD];
__device__ float g_qwe[NN * 8];
__device__ float2 g_dc[NN * 8];
__device__ float g_out[(size_t)NN * HD];
__device__ int   g_srcdst[2 * EE];
__device__ int   g_is64;
// CSR by dst
__device__ int   g_cnt[NN];
__device__ int   g_cur[NN];
__device__ int   g_off[NN + 1];
__device__ int   g_esrc[EE];
__device__ float g_eew[EE];

__device__ __forceinline__ float tf32_hi(float v) {
    uint32_t h;
    asm("cvt.rna.tf32.f32 %0, %1;" : "=r"(h) : "f"(v));
    return __uint_as_float(h);
}

// m16n8k8 tf32 mma (baseline sm_80+ PTX; runs on tensor pipe on sm_103)
__device__ __forceinline__ void mma_tf32(float* c, const uint32_t* a, const uint32_t* b) {
    asm volatile(
        "mma.sync.aligned.m16n8k8.row.col.f32.tf32.tf32.f32 "
        "{%0,%1,%2,%3}, {%4,%5,%6,%7}, {%8,%9}, {%0,%1,%2,%3};"
        : "+f"(c[0]), "+f"(c[1]), "+f"(c[2]), "+f"(c[3])
        : "r"(a[0]), "r"(a[1]), "r"(a[2]), "r"(a[3]), "r"(b[0]), "r"(b[1]));
}

// ---------------- edge index dtype detect + convert ----------------
__global__ void detect_kernel(const void* ei) {
    if (blockIdx.x == 0 && threadIdx.x == 0) {
        const int* w = (const int*)ei;
        int all_zero = 1;
        for (int i = 0; i < 32; i++) {
            if (w[2 * i + 1] != 0) { all_zero = 0; break; }
        }
        g_is64 = all_zero;
    }
}

__global__ void convert_kernel(const void* ei) {
    int i = blockIdx.x * blockDim.x + threadIdx.x;
    if (i >= 2 * EE) return;
    if (g_is64)
        g_srcdst[i] = (int)((const long long*)ei)[i];
    else
        g_srcdst[i] = ((const int*)ei)[i];
}

// ---------------- CSR build ----------------
__global__ void zero_cnt(void) {
    int i = blockIdx.x * blockDim.x + threadIdx.x;
    if (i < NN) g_cnt[i] = 0;
}

__global__ void count_kernel(void) {
    int e = blockIdx.x * blockDim.x + threadIdx.x;
    if (e < EE) atomicAdd(&g_cnt[g_srcdst[EE + e]], 1);
}

__global__ void scan_kernel(void) {
    __shared__ int s[1024];
    int t = threadIdx.x;
    int base = t * 10;
    int local[10];
    int sum = 0;
#pragma unroll
    for (int i = 0; i < 10; i++) {
        int idx = base + i;
        int v = (idx < NN) ? g_cnt[idx] : 0;
        local[i] = v; sum += v;
    }
    s[t] = sum;
    __syncthreads();
    for (int off = 1; off < 1024; off <<= 1) {
        int v = (t >= off) ? s[t - off] : 0;
        __syncthreads();
        if (t >= off) s[t] += v;
        __syncthreads();
    }
    int excl = (t == 0) ? 0 : s[t - 1];
#pragma unroll
    for (int i = 0; i < 10; i++) {
        int idx = base + i;
        if (idx < NN) { g_off[idx] = excl; g_cur[idx] = 0; }
        excl += local[i];
    }
    if (t == 1023) g_off[NN] = s[1023];
}

__global__ void scatter_kernel(const float* __restrict__ ew) {
    int e = blockIdx.x * blockDim.x + threadIdx.x;
    if (e >= EE) return;
    int d = g_srcdst[EE + e];
    int pos = g_off[d] + atomicAdd(&g_cur[d], 1);
    g_esrc[pos] = g_srcdst[e];
    g_eew[pos] = ew[e];
}

// ---------------- weight packing: W hi/lo planes in [k][n] layout + bias + Wqe fold ----------------
__global__ void pack_kernel(const float* __restrict__ Wq, const float* __restrict__ bq,
                            const float* __restrict__ Wk, const float* __restrict__ bk,
                            const float* __restrict__ Wv, const float* __restrict__ bv,
                            const float* __restrict__ Ws, const float* __restrict__ bs,
                            const float* __restrict__ We,
                            float* __restrict__ Whi, float* __restrict__ Wlo,
                            float* __restrict__ bp,
                            float* __restrict__ Wqe, float* __restrict__ bqe) {
    int i = blockIdx.x * blockDim.x + threadIdx.x;
    if (i >= 256 * QK) return;
    int k = i >> 10, n = i & 1023;
    const float* W; const float* b; int cc;
    if (n < 256)      { W = Wq; b = bq; cc = n; }
    else if (n < 512) { W = Wk; b = bk; cc = n - 256; }
    else if (n < 768) { W = Wv; b = bv; cc = n - 512; }
    else              { W = Ws; b = bs; cc = n - 768; }
    float v = W[k * 256 + cc];
    float hf = tf32_hi(v);
    Whi[i] = hf;
    Wlo[i] = tf32_hi(v - hf);
    if (k == 0) bp[n] = b[cc];
    if (i < 2048) {
        int rr = i >> 3, h = i & 7;
        float s = 0.f;
#pragma unroll
        for (int t = 0; t < 32; t++) s += Wq[rr * 256 + h * 32 + t] * We[h * 32 + t];
        Wqe[rr * 8 + h] = s;
    }
    if (i < 8) {
        float s = 0.f;
#pragma unroll
        for (int t = 0; t < 32; t++) s += bq[i * 32 + t] * We[i * 32 + t];
        bqe[i] = s;
    }
}

// ---------------- per-layer input split: x -> hi/lo tf32 planes ----------------
__global__ void split_kernel(const float* __restrict__ x) {
    int i = blockIdx.x * blockDim.x + threadIdx.x;
    if (i >= NN * 256) return;
    float v = x[i];
    float hf = tf32_hi(v);
    g_Ahi[i] = hf;
    g_Alo[i] = tf32_hi(v - hf);
}

// ---------------- per-node q.We ----------------
__global__ void qwe_kernel(const float* __restrict__ x, const float* __restrict__ Wqe,
                           const float* __restrict__ bqe) {
    int gt = blockIdx.x * blockDim.x + threadIdx.x;
    int node = gt >> 5, lane = gt & 31;
    if (node >= NN) return;
    float xv[8];
#pragma unroll
    for (int j = 0; j < 8; j++) xv[j] = x[(size_t)node * 256 + j * 32 + lane];
    float p[8];
#pragma unroll
    for (int h = 0; h < 8; h++) {
        float s = 0.f;
#pragma unroll
        for (int j = 0; j < 8; j++) s += xv[j] * Wqe[(j * 32 + lane) * 8 + h];
#pragma unroll
        for (int off = 16; off; off >>= 1) s += __shfl_xor_sync(0xffffffffu, s, off);
        p[h] = s;
    }
    if (lane < 8) g_qwe[node * 8 + lane] = p[lane] + bqe[lane];
}

// ---------------- mma.sync tf32 GEMM (3xTF32): C[N,1024] = X @ W + bp ----------------
// Block 128x128, BK=32, 8 warps (2x4), warp tile 64x32, m16n8k8 fragments.
#define AS_STRIDE 36
#define BS_STRIDE 132

__global__ __launch_bounds__(256, 2)
void gemm_mma(const float* __restrict__ Whi, const float* __restrict__ Wlo,
              const float* __restrict__ bp, float* __restrict__ C) {
    __shared__ float As[128][AS_STRIDE];   // [m][k]
    __shared__ float Bs[32][BS_STRIDE];    // [k][n]

    int tid = threadIdx.x;
    int wid = tid >> 5, lane = tid & 31;
    int warpM = (wid & 1) * 64;    // 2 warps over M
    int warpN = (wid >> 1) * 32;   // 4 warps over N
    int rowBase = blockIdx.y * 128, colBase = blockIdx.x * 128;
    int lq = lane & 3, lg = lane >> 2;   // quad id / group id

    float acc[4][4][4];   // [mtile][ntile][4]
#pragma unroll
    for (int mt = 0; mt < 4; mt++)
#pragma unroll
        for (int nt = 0; nt < 4; nt++)
#pragma unroll
            for (int r = 0; r < 4; r++) acc[mt][nt][r] = 0.f;

    const float* Apl[3] = { g_Ahi, g_Alo, g_Ahi };
    const float* Bpl[3] = { Whi, Whi, Wlo };

    for (int p = 0; p < 3; p++) {
        const float* Ap = Apl[p];
        const float* Bp = Bpl[p];
        for (int c = 0; c < 8; c++) {
            int k0 = c * 32;
            // A copy-in: 128 rows x 32 floats
#pragma unroll
            for (int it = 0; it < 4; it++) {
                int idx = tid + it * 256;
                int m = idx >> 3, q = idx & 7;
                int arow = rowBase + m;
                float4 v = make_float4(0.f, 0.f, 0.f, 0.f);
                if (arow < NN) v = *(const float4*)(Ap + (size_t)arow * 256 + k0 + q * 4);
                *(float4*)(&As[m][q * 4]) = v;
            }
            // B copy-in: 32 k-rows x 128 floats (already [k][n] in global)
#pragma unroll
            for (int it = 0; it < 4; it++) {
                int idx = tid + it * 256;
                int k = idx >> 5, n4 = idx & 31;
                float4 v = *(const float4*)(Bp + (size_t)(k0 + k) * QK + colBase + n4 * 4);
                *(float4*)(&Bs[k][n4 * 4]) = v;
            }
            __syncthreads();
#pragma unroll
            for (int ks = 0; ks < 4; ks++) {
                int kk = ks * 8;
                uint32_t af[4][4], bf[4][2];
#pragma unroll
                for (int mt = 0; mt < 4; mt++) {
                    int m = warpM + mt * 16 + lg;
                    af[mt][0] = __float_as_uint(As[m][kk + lq]);
                    af[mt][1] = __float_as_uint(As[m + 8][kk + lq]);
                    af[mt][2] = __float_as_uint(As[m][kk + lq + 4]);
                    af[mt][3] = __float_as_uint(As[m + 8][kk + lq + 4]);
                }
#pragma unroll
                for (int nt = 0; nt < 4; nt++) {
                    int n = warpN + nt * 8 + lg;
                    bf[nt][0] = __float_as_uint(Bs[kk + lq][n]);
                    bf[nt][1] = __float_as_uint(Bs[kk + lq + 4][n]);
                }
#pragma unroll
                for (int mt = 0; mt < 4; mt++)
#pragma unroll
                    for (int nt = 0; nt < 4; nt++)
                        mma_tf32(acc[mt][nt], af[mt], bf[nt]);
            }
            __syncthreads();
        }
    }

    // epilogue: bias + store. c0/c1: (row, col..col+1); c2/c3: (row+8, ...)
#pragma unroll
    for (int mt = 0; mt < 4; mt++) {
        int row = rowBase + warpM + mt * 16 + lg;
#pragma unroll
        for (int nt = 0; nt < 4; nt++) {
            int col = colBase + warpN + nt * 8 + 2 * lq;
            float2 bb = *(const float2*)(bp + col);
            if (row < NN) {
                float2 o0 = make_float2(acc[mt][nt][0] + bb.x, acc[mt][nt][1] + bb.y);
                *(float2*)(C + (size_t)row * QK + col) = o0;
            }
            if (row + 8 < NN) {
                float2 o1 = make_float2(acc[mt][nt][2] + bb.x, acc[mt][nt][3] + bb.y);
                *(float2*)(C + (size_t)(row + 8) * QK + col) = o1;
            }
        }
    }
}

// ---------------- CSR gather attention: one warp per (node, head), no atomics ----------------
__global__ __launch_bounds__(256)
void agg_kernel(const float* __restrict__ qwe) {
    int warpId = (blockIdx.x * blockDim.x + threadIdx.x) >> 5;
    int lane = threadIdx.x & 31;
    if (warpId >= NN * 8) return;
    int node = warpId >> 3, h = warpId & 7;
    float q = g_qkvs[(size_t)node * QK + h * 32 + lane];
    float qw = qwe[node * 8 + h];
    int beg = g_off[node], end = g_off[node + 1];

    float acc = 0.f, denom = 0.f, coeff = 0.f;

    float w0 = 0.f, k0 = 0.f, v0 = 0.f;
    float w1 = 0.f, k1 = 0.f, v1 = 0.f;
    if (beg < end) {
        int s = g_esrc[beg]; w0 = g_eew[beg];
        k0 = g_qkvs[(size_t)s * QK + 256 + h * 32 + lane];
        v0 = g_qkvs[(size_t)s * QK + 512 + h * 32 + lane];
    }
    if (beg + 1 < end) {
        int s = g_esrc[beg + 1]; w1 = g_eew[beg + 1];
        k1 = g_qkvs[(size_t)s * QK + 256 + h * 32 + lane];
        v1 = g_qkvs[(size_t)s * QK + 512 + h * 32 + lane];
    }
    for (int i = beg; i < end; i++) {
        float w2 = 0.f, k2 = 0.f, v2 = 0.f;
        if (i + 2 < end) {
            int s = g_esrc[i + 2]; w2 = g_eew[i + 2];
            k2 = g_qkvs[(size_t)s * QK + 256 + h * 32 + lane];
            v2 = g_qkvs[(size_t)s * QK + 512 + h * 32 + lane];
        }
        float dv = q * k0;
#pragma unroll
        for (int off = 16; off; off >>= 1)
            dv += __shfl_xor_sync(0xffffffffu, dv, off);
        float ex = __expf((dv + w0 * qw) * 0.17677669529663687f);
        denom += ex;
        coeff += ex * w0;
        acc += ex * v0;
        w0 = w1; k0 = k1; v0 = v1;
        w1 = w2; k1 = k2; v1 = v2;
    }
    g_out[(size_t)node * HD + h * 32 + lane] = acc;
    if (lane == 0) g_dc[node * 8 + h] = make_float2(denom, coeff);
}

// ---------------- finalize: normalize (+ coeff*We), gated skip ----------------
__global__ void finalize(const float* __restrict__ Wb, const float* __restrict__ We,
                         float* __restrict__ hout) {
    int gt = blockIdx.x * blockDim.x + threadIdx.x;
    int node = gt >> 5;
    int lane = gt & 31;
    if (node >= NN) return;
    const float* xr = g_qkvs + (size_t)node * QK + 768;
    const float* oa = g_out + (size_t)node * HD;
    float o[8], x[8];
    float dot = 0.f;
#pragma unroll
    for (int j = 0; j < 8; j++) {
        int c = j * 32 + lane;
        float2 dc = g_dc[node * 8 + j];
        float ov = (oa[c] + dc.y * We[c]) / (dc.x + 1e-16f);
        float xv = xr[c];
        o[j] = ov; x[j] = xv;
        dot += ov * Wb[c] + xv * Wb[256 + c] + (ov - xv) * Wb[512 + c];
    }
#pragma unroll
    for (int off = 16; off; off >>= 1)
        dot += __shfl_xor_sync(0xffffffffu, dot, off);
    float beta = 1.f / (1.f + __expf(-dot));
#pragma unroll
    for (int j = 0; j < 8; j++)
        hout[(size_t)node * HD + j * 32 + lane] = beta * x[j] + (1.f - beta) * o[j];
}

// ---------------- host orchestration ----------------
static void run_layer(const float* xin, const float* Whi, const float* Wlo,
                      const float* bp, const float* Wqe, const float* bqe,
                      const float* We, const float* Wb, float* hout) {
    float* qkvs; cudaGetSymbolAddress((void**)&qkvs, g_qkvs);
    float* qwe;  cudaGetSymbolAddress((void**)&qwe, g_qwe);
    split_kernel<<<(NN * 256 + 255) / 256, 256>>>(xin);
    qwe_kernel<<<(NN * 32 + 255) / 256, 256>>>(xin, Wqe, bqe);
    dim3 gg(QK / 128, (NN + 127) / 128);
    gemm_mma<<<gg, 256>>>(Whi, Wlo, bp, qkvs);
    agg_kernel<<<(NN * 8 * 32 + 255) / 256, 256>>>(qwe);
    finalize<<<(NN * 32 + 127) / 128, 128>>>(Wb, We, hout);
}

extern "C" void kernel_launch(void* const* d_in, const int* in_sizes, int n_in,
                              void* d_out, int out_size) {
    const float* x  = (const float*)d_in[0];
    const void*  ei = d_in[1];
    const float* ew = (const float*)d_in[2];
    const float* Wq1 = (const float*)d_in[3];  const float* bq1 = (const float*)d_in[4];
    const float* Wk1 = (const float*)d_in[5];  const float* bk1 = (const float*)d_in[6];
    const float* Wv1 = (const float*)d_in[7];  const float* bv1 = (const float*)d_in[8];
    const float* We1 = (const float*)d_in[9];
    const float* Ws1 = (const float*)d_in[10]; const float* bs1 = (const float*)d_in[11];
    const float* Wb1 = (const float*)d_in[12];
    const float* Wq2 = (const float*)d_in[13]; const float* bq2 = (const float*)d_in[14];
    const float* Wk2 = (const float*)d_in[15]; const float* bk2 = (const float*)d_in[16];
    const float* Wv2 = (const float*)d_in[17]; const float* bv2 = (const float*)d_in[18];
    const float* We2 = (const float*)d_in[19];
    const float* Ws2 = (const float*)d_in[20]; const float* bs2 = (const float*)d_in[21];
    const float* Wb2 = (const float*)d_in[22];

    float *Whi1, *Wlo1, *bp1, *Whi2, *Wlo2, *bp2;
    float *Wqe1, *bqe1, *Wqe2, *bqe2, *h1, *h2;
    cudaGetSymbolAddress((void**)&Whi1, g_Whi1);
    cudaGetSymbolAddress((void**)&Wlo1, g_Wlo1);
    cudaGetSymbolAddress((void**)&bp1, g_bp1);
    cudaGetSymbolAddress((void**)&Whi2, g_Whi2);
    cudaGetSymbolAddress((void**)&Wlo2, g_Wlo2);
    cudaGetSymbolAddress((void**)&bp2, g_bp2);
    cudaGetSymbolAddress((void**)&Wqe1, g_Wqe1);
    cudaGetSymbolAddress((void**)&bqe1, g_bqe1);
    cudaGetSymbolAddress((void**)&Wqe2, g_Wqe2);
    cudaGetSymbolAddress((void**)&bqe2, g_bqe2);
    cudaGetSymbolAddress((void**)&h1, g_h1);
    cudaGetSymbolAddress((void**)&h2, g_h2);

    detect_kernel<<<1, 32>>>(ei);
    convert_kernel<<<(2 * EE + 255) / 256, 256>>>(ei);

    // CSR build (graph-capturable)
    zero_cnt<<<(NN + 255) / 256, 256>>>();
    count_kernel<<<(EE + 255) / 256, 256>>>();
    scan_kernel<<<1, 1024>>>();
    scatter_kernel<<<(EE + 255) / 256, 256>>>(ew);

    pack_kernel<<<(256 * QK + 255) / 256, 256>>>(Wq1, bq1, Wk1, bk1, Wv1, bv1, Ws1, bs1,
                                                 We1, Whi1, Wlo1, bp1, Wqe1, bqe1);
    pack_kernel<<<(256 * QK + 255) / 256, 256>>>(Wq2, bq2, Wk2, bk2, Wv2, bv2, Ws2, bs2,
                                                 We2, Whi2, Wlo2, bp2, Wqe2, bqe2);

    run_layer(x,  Whi1, Wlo1, bp1, Wqe1, bqe1, We1, Wb1, h1);
    run_layer(h1, Whi2, Wlo2, bp2, Wqe2, bqe2, We2, Wb2, h2);
    run_layer(h2, Whi2, Wlo2, bp2, Wqe2, bqe2, We2, Wb2, (float*)d_out);
}

// round 14
// speedup vs baseline: 1.8684x; 1.0059x over previous
#include <cuda_runtime.h>
#include <cuda_bf16.h>
#include <math_constants.h>
#include <cstdint>

#define NN 10000
#define EE 320000
#define HD 256      // heads*dim
#define QK 1024     // q|k|v|skip packed width

// ---------------- scratch (device globals; no allocation allowed) ----------------
__device__ float g_Whi1[256 * QK];    // W hi plane, [k][n] layout
__device__ float g_Wlo1[256 * QK];    // W lo plane (tf32-rounded)
__device__ float g_bp1[QK];
__device__ float g_Whi2[256 * QK];
__device__ float g_Wlo2[256 * QK];
__device__ float g_bp2[QK];
__device__ float g_Wqe1[256 * 8];
__device__ float g_bqe1[8];
__device__ float g_Wqe2[256 * 8];
__device__ float g_bqe2[8];
__device__ float g_Ahi[(size_t)NN * 256];   // x hi plane [m][k]
__device__ float g_Alo[(size_t)NN * 256];   // x lo plane (tf32-rounded)
__device__ float g_qkvs[(size_t)NN * QK];   // 40 MB
__device__ float g_h1[(size_t)NN * HD];
__device__ float g_h2[(size_t)NN * HD];
__device__ float g_qwe[NN * 8];
__device__ float2 g_dc[NN * 8];
__device__ float g_out[(size_t)NN * HD];
__device__ int   g_srcdst[2 * EE];
__device__ int   g_is64;
// CSR by dst
__device__ int   g_cnt[NN];
__device__ int   g_cur[NN];
__device__ int   g_off[NN + 1];
__device__ int   g_esrc[EE];
__device__ float g_eew[EE];

__device__ __forceinline__ float tf32_hi(float v) {
    uint32_t h;
    asm("cvt.rna.tf32.f32 %0, %1;" : "=r"(h) : "f"(v));
    return __uint_as_float(h);
}

// m16n8k8 tf32 mma (baseline sm_80+ PTX; tensor pipe on sm_103)
__device__ __forceinline__ void mma_tf32(float* c, const uint32_t* a, const uint32_t* b) {
    asm volatile(
        "mma.sync.aligned.m16n8k8.row.col.f32.tf32.tf32.f32 "
        "{%0,%1,%2,%3}, {%4,%5,%6,%7}, {%8,%9}, {%0,%1,%2,%3};"
        : "+f"(c[0]), "+f"(c[1]), "+f"(c[2]), "+f"(c[3])
        : "r"(a[0]), "r"(a[1]), "r"(a[2]), "r"(a[3]), "r"(b[0]), "r"(b[1]));
}

// ---------------- edge index dtype detect + convert ----------------
__global__ void detect_kernel(const void* ei) {
    if (blockIdx.x == 0 && threadIdx.x == 0) {
        const int* w = (const int*)ei;
        int all_zero = 1;
        for (int i = 0; i < 32; i++) {
            if (w[2 * i + 1] != 0) { all_zero = 0; break; }
        }
        g_is64 = all_zero;
    }
}

__global__ void convert_kernel(const void* ei) {
    int i = blockIdx.x * blockDim.x + threadIdx.x;
    if (i >= 2 * EE) return;
    if (g_is64)
        g_srcdst[i] = (int)((const long long*)ei)[i];
    else
        g_srcdst[i] = ((const int*)ei)[i];
}

// ---------------- CSR build ----------------
__global__ void zero_cnt(void) {
    int i = blockIdx.x * blockDim.x + threadIdx.x;
    if (i < NN) g_cnt[i] = 0;
}

__global__ void count_kernel(void) {
    int e = blockIdx.x * blockDim.x + threadIdx.x;
    if (e < EE) atomicAdd(&g_cnt[g_srcdst[EE + e]], 1);
}

__global__ void scan_kernel(void) {
    __shared__ int s[1024];
    int t = threadIdx.x;
    int base = t * 10;
    int local[10];
    int sum = 0;
#pragma unroll
    for (int i = 0; i < 10; i++) {
        int idx = base + i;
        int v = (idx < NN) ? g_cnt[idx] : 0;
        local[i] = v; sum += v;
    }
    s[t] = sum;
    __syncthreads();
    for (int off = 1; off < 1024; off <<= 1) {
        int v = (t >= off) ? s[t - off] : 0;
        __syncthreads();
        if (t >= off) s[t] += v;
        __syncthreads();
    }
    int excl = (t == 0) ? 0 : s[t - 1];
#pragma unroll
    for (int i = 0; i < 10; i++) {
        int idx = base + i;
        if (idx < NN) { g_off[idx] = excl; g_cur[idx] = 0; }
        excl += local[i];
    }
    if (t == 1023) g_off[NN] = s[1023];
}

__global__ void scatter_kernel(const float* __restrict__ ew) {
    int e = blockIdx.x * blockDim.x + threadIdx.x;
    if (e >= EE) return;
    int d = g_srcdst[EE + e];
    int pos = g_off[d] + atomicAdd(&g_cur[d], 1);
    g_esrc[pos] = g_srcdst[e];
    g_eew[pos] = ew[e];
}

// ---------------- weight packing: W hi/lo planes in [k][n] layout + bias + Wqe fold ----------------
__global__ void pack_kernel(const float* __restrict__ Wq, const float* __restrict__ bq,
                            const float* __restrict__ Wk, const float* __restrict__ bk,
                            const float* __restrict__ Wv, const float* __restrict__ bv,
                            const float* __restrict__ Ws, const float* __restrict__ bs,
                            const float* __restrict__ We,
                            float* __restrict__ Whi, float* __restrict__ Wlo,
                            float* __restrict__ bp,
                            float* __restrict__ Wqe, float* __restrict__ bqe) {
    int i = blockIdx.x * blockDim.x + threadIdx.x;
    if (i >= 256 * QK) return;
    int k = i >> 10, n = i & 1023;
    const float* W; const float* b; int cc;
    if (n < 256)      { W = Wq; b = bq; cc = n; }
    else if (n < 512) { W = Wk; b = bk; cc = n - 256; }
    else if (n < 768) { W = Wv; b = bv; cc = n - 512; }
    else              { W = Ws; b = bs; cc = n - 768; }
    float v = W[k * 256 + cc];
    float hf = tf32_hi(v);
    Whi[i] = hf;
    Wlo[i] = tf32_hi(v - hf);
    if (k == 0) bp[n] = b[cc];
    if (i < 2048) {
        int rr = i >> 3, h = i & 7;
        float s = 0.f;
#pragma unroll
        for (int t = 0; t < 32; t++) s += Wq[rr * 256 + h * 32 + t] * We[h * 32 + t];
        Wqe[rr * 8 + h] = s;
    }
    if (i < 8) {
        float s = 0.f;
#pragma unroll
        for (int t = 0; t < 32; t++) s += bq[i * 32 + t] * We[i * 32 + t];
        bqe[i] = s;
    }
}

// ---------------- layer-1 input split: x -> hi/lo tf32 planes ----------------
__global__ void split_kernel(const float* __restrict__ x) {
    int i = blockIdx.x * blockDim.x + threadIdx.x;
    if (i >= NN * 256) return;
    float v = x[i];
    float hf = tf32_hi(v);
    g_Ahi[i] = hf;
    g_Alo[i] = tf32_hi(v - hf);
}

// ---------------- per-node q.We ----------------
__global__ void qwe_kernel(const float* __restrict__ x, const float* __restrict__ Wqe,
                           const float* __restrict__ bqe) {
    int gt = blockIdx.x * blockDim.x + threadIdx.x;
    int node = gt >> 5, lane = gt & 31;
    if (node >= NN) return;
    float xv[8];
#pragma unroll
    for (int j = 0; j < 8; j++) xv[j] = x[(size_t)node * 256 + j * 32 + lane];
    float p[8];
#pragma unroll
    for (int h = 0; h < 8; h++) {
        float s = 0.f;
#pragma unroll
        for (int j = 0; j < 8; j++) s += xv[j] * Wqe[(j * 32 + lane) * 8 + h];
#pragma unroll
        for (int off = 16; off; off >>= 1) s += __shfl_xor_sync(0xffffffffu, s, off);
        p[h] = s;
    }
    if (lane < 8) g_qwe[node * 8 + lane] = p[lane] + bqe[lane];
}

// ---------------- mma.sync tf32 GEMM (3xTF32): C[N,1024] = X @ W + bp ----------------
// Block 128x128, BK=32, 8 warps (2x4), warp tile 64x32, m16n8k8 fragments.
#define AS_STRIDE 36
#define BS_STRIDE 132

__global__ __launch_bounds__(256, 2)
void gemm_mma(const float* __restrict__ Whi, const float* __restrict__ Wlo,
              const float* __restrict__ bp, float* __restrict__ C) {
    __shared__ float As[128][AS_STRIDE];   // [m][k]
    __shared__ float Bs[32][BS_STRIDE];    // [k][n]

    int tid = threadIdx.x;
    int wid = tid >> 5, lane = tid & 31;
    int warpM = (wid & 1) * 64;    // 2 warps over M
    int warpN = (wid >> 1) * 32;   // 4 warps over N
    int rowBase = blockIdx.y * 128, colBase = blockIdx.x * 128;
    int lq = lane & 3, lg = lane >> 2;   // quad id / group id

    float acc[4][4][4];   // [mtile][ntile][4]
#pragma unroll
    for (int mt = 0; mt < 4; mt++)
#pragma unroll
        for (int nt = 0; nt < 4; nt++)
#pragma unroll
            for (int r = 0; r < 4; r++) acc[mt][nt][r] = 0.f;

    const float* Apl[3] = { g_Ahi, g_Alo, g_Ahi };
    const float* Bpl[3] = { Whi, Whi, Wlo };

    for (int p = 0; p < 3; p++) {
        const float* Ap = Apl[p];
        const float* Bp = Bpl[p];
        for (int c = 0; c < 8; c++) {
            int k0 = c * 32;
            // A copy-in: 128 rows x 32 floats
#pragma unroll
            for (int it = 0; it < 4; it++) {
                int idx = tid + it * 256;
                int m = idx >> 3, q = idx & 7;
                int arow = rowBase + m;
                float4 v = make_float4(0.f, 0.f, 0.f, 0.f);
                if (arow < NN) v = *(const float4*)(Ap + (size_t)arow * 256 + k0 + q * 4);
                *(float4*)(&As[m][q * 4]) = v;
            }
            // B copy-in: 32 k-rows x 128 floats (already [k][n] in global)
#pragma unroll
            for (int it = 0; it < 4; it++) {
                int idx = tid + it * 256;
                int k = idx >> 5, n4 = idx & 31;
                float4 v = *(const float4*)(Bp + (size_t)(k0 + k) * QK + colBase + n4 * 4);
                *(float4*)(&Bs[k][n4 * 4]) = v;
            }
            __syncthreads();
#pragma unroll
            for (int ks = 0; ks < 4; ks++) {
                int kk = ks * 8;
                uint32_t af[4][4], bf[4][2];
#pragma unroll
                for (int mt = 0; mt < 4; mt++) {
                    int m = warpM + mt * 16 + lg;
                    af[mt][0] = __float_as_uint(As[m][kk + lq]);
                    af[mt][1] = __float_as_uint(As[m + 8][kk + lq]);
                    af[mt][2] = __float_as_uint(As[m][kk + lq + 4]);
                    af[mt][3] = __float_as_uint(As[m + 8][kk + lq + 4]);
                }
#pragma unroll
                for (int nt = 0; nt < 4; nt++) {
                    int n = warpN + nt * 8 + lg;
                    bf[nt][0] = __float_as_uint(Bs[kk + lq][n]);
                    bf[nt][1] = __float_as_uint(Bs[kk + lq + 4][n]);
                }
#pragma unroll
                for (int mt = 0; mt < 4; mt++)
#pragma unroll
                    for (int nt = 0; nt < 4; nt++)
                        mma_tf32(acc[mt][nt], af[mt], bf[nt]);
            }
            __syncthreads();
        }
    }

    // epilogue: bias + store. c0/c1: (row, col..col+1); c2/c3: (row+8, ...)
#pragma unroll
    for (int mt = 0; mt < 4; mt++) {
        int row = rowBase + warpM + mt * 16 + lg;
#pragma unroll
        for (int nt = 0; nt < 4; nt++) {
            int col = colBase + warpN + nt * 8 + 2 * lq;
            float2 bb = *(const float2*)(bp + col);
            if (row < NN) {
                float2 o0 = make_float2(acc[mt][nt][0] + bb.x, acc[mt][nt][1] + bb.y);
                *(float2*)(C + (size_t)row * QK + col) = o0;
            }
            if (row + 8 < NN) {
                float2 o1 = make_float2(acc[mt][nt][2] + bb.x, acc[mt][nt][3] + bb.y);
                *(float2*)(C + (size_t)(row + 8) * QK + col) = o1;
            }
        }
    }
}

// ---------------- CSR gather attention: one warp per (node, head), no atomics ----------------
__global__ __launch_bounds__(256)
void agg_kernel(const float* __restrict__ qwe) {
    int warpId = (blockIdx.x * blockDim.x + threadIdx.x) >> 5;
    int lane = threadIdx.x & 31;
    if (warpId >= NN * 8) return;
    int node = warpId >> 3, h = warpId & 7;
    float q = g_qkvs[(size_t)node * QK + h * 32 + lane];
    float qw = qwe[node * 8 + h];
    int beg = g_off[node], end = g_off[node + 1];

    float acc = 0.f, denom = 0.f, coeff = 0.f;

    float w0 = 0.f, k0 = 0.f, v0 = 0.f;
    float w1 = 0.f, k1 = 0.f, v1 = 0.f;
    if (beg < end) {
        int s = g_esrc[beg]; w0 = g_eew[beg];
        k0 = g_qkvs[(size_t)s * QK + 256 + h * 32 + lane];
        v0 = g_qkvs[(size_t)s * QK + 512 + h * 32 + lane];
    }
    if (beg + 1 < end) {
        int s = g_esrc[beg + 1]; w1 = g_eew[beg + 1];
        k1 = g_qkvs[(size_t)s * QK + 256 + h * 32 + lane];
        v1 = g_qkvs[(size_t)s * QK + 512 + h * 32 + lane];
    }
    for (int i = beg; i < end; i++) {
        float w2 = 0.f, k2 = 0.f, v2 = 0.f;
        if (i + 2 < end) {
            int s = g_esrc[i + 2]; w2 = g_eew[i + 2];
            k2 = g_qkvs[(size_t)s * QK + 256 + h * 32 + lane];
            v2 = g_qkvs[(size_t)s * QK + 512 + h * 32 + lane];
        }
        float dv = q * k0;
#pragma unroll
        for (int off = 16; off; off >>= 1)
            dv += __shfl_xor_sync(0xffffffffu, dv, off);
        float ex = __expf((dv + w0 * qw) * 0.17677669529663687f);
        denom += ex;
        coeff += ex * w0;
        acc += ex * v0;
        w0 = w1; k0 = k1; v0 = v1;
        w1 = w2; k1 = k2; v1 = v2;
    }
    g_out[(size_t)node * HD + h * 32 + lane] = acc;
    if (lane == 0) g_dc[node * 8 + h] = make_float2(denom, coeff);
}

// ---------------- finalize: normalize (+ coeff*We), gated skip; fused hi/lo split ----------------
__global__ void finalize(const float* __restrict__ Wb, const float* __restrict__ We,
                         float* __restrict__ hout, int do_split) {
    int gt = blockIdx.x * blockDim.x + threadIdx.x;
    int node = gt >> 5;
    int lane = gt & 31;
    if (node >= NN) return;
    const float* xr = g_qkvs + (size_t)node * QK + 768;
    const float* oa = g_out + (size_t)node * HD;
    float o[8], x[8];
    float dot = 0.f;
#pragma unroll
    for (int j = 0; j < 8; j++) {
        int c = j * 32 + lane;
        float2 dc = g_dc[node * 8 + j];
        float ov = (oa[c] + dc.y * We[c]) / (dc.x + 1e-16f);
        float xv = xr[c];
        o[j] = ov; x[j] = xv;
        dot += ov * Wb[c] + xv * Wb[256 + c] + (ov - xv) * Wb[512 + c];
    }
#pragma unroll
    for (int off = 16; off; off >>= 1)
        dot += __shfl_xor_sync(0xffffffffu, dot, off);
    float beta = 1.f / (1.f + __expf(-dot));
#pragma unroll
    for (int j = 0; j < 8; j++) {
        size_t idx = (size_t)node * HD + j * 32 + lane;
        float hv = beta * x[j] + (1.f - beta) * o[j];
        hout[idx] = hv;
        if (do_split) {
            float hf = tf32_hi(hv);
            g_Ahi[idx] = hf;
            g_Alo[idx] = tf32_hi(hv - hf);
        }
    }
}

// ---------------- host orchestration ----------------
static void run_layer(const float* xin, const float* Whi, const float* Wlo,
                      const float* bp, const float* Wqe, const float* bqe,
                      const float* We, const float* Wb, float* hout, int do_split) {
    float* qkvs; cudaGetSymbolAddress((void**)&qkvs, g_qkvs);
    float* qwe;  cudaGetSymbolAddress((void**)&qwe, g_qwe);
    dim3 gg(QK / 128, (NN + 127) / 128);
    gemm_mma<<<gg, 256>>>(Whi, Wlo, bp, qkvs);
    qwe_kernel<<<(NN * 32 + 255) / 256, 256>>>(xin, Wqe, bqe);
    agg_kernel<<<(NN * 8 * 32 + 255) / 256, 256>>>(qwe);
    finalize<<<(NN * 32 + 127) / 128, 128>>>(Wb, We, hout, do_split);
}

extern "C" void kernel_launch(void* const* d_in, const int* in_sizes, int n_in,
                              void* d_out, int out_size) {
    const float* x  = (const float*)d_in[0];
    const void*  ei = d_in[1];
    const float* ew = (const float*)d_in[2];
    const float* Wq1 = (const float*)d_in[3];  const float* bq1 = (const float*)d_in[4];
    const float* Wk1 = (const float*)d_in[5];  const float* bk1 = (const float*)d_in[6];
    const float* Wv1 = (const float*)d_in[7];  const float* bv1 = (const float*)d_in[8];
    const float* We1 = (const float*)d_in[9];
    const float* Ws1 = (const float*)d_in[10]; const float* bs1 = (const float*)d_in[11];
    const float* Wb1 = (const float*)d_in[12];
    const float* Wq2 = (const float*)d_in[13]; const float* bq2 = (const float*)d_in[14];
    const float* Wk2 = (const float*)d_in[15]; const float* bk2 = (const float*)d_in[16];
    const float* Wv2 = (const float*)d_in[17]; const float* bv2 = (const float*)d_in[18];
    const float* We2 = (const float*)d_in[19];
    const float* Ws2 = (const float*)d_in[20]; const float* bs2 = (const float*)d_in[21];
    const float* Wb2 = (const float*)d_in[22];

    float *Whi1, *Wlo1, *bp1, *Whi2, *Wlo2, *bp2;
    float *Wqe1, *bqe1, *Wqe2, *bqe2, *h1, *h2;
    cudaGetSymbolAddress((void**)&Whi1, g_Whi1);
    cudaGetSymbolAddress((void**)&Wlo1, g_Wlo1);
    cudaGetSymbolAddress((void**)&bp1, g_bp1);
    cudaGetSymbolAddress((void**)&Whi2, g_Whi2);
    cudaGetSymbolAddress((void**)&Wlo2, g_Wlo2);
    cudaGetSymbolAddress((void**)&bp2, g_bp2);
    cudaGetSymbolAddress((void**)&Wqe1, g_Wqe1);
    cudaGetSymbolAddress((void**)&bqe1, g_bqe1);
    cudaGetSymbolAddress((void**)&Wqe2, g_Wqe2);
    cudaGetSymbolAddress((void**)&bqe2, g_bqe2);
    cudaGetSymbolAddress((void**)&h1, g_h1);
    cudaGetSymbolAddress((void**)&h2, g_h2);

    // launches 0-2: packing + layer-1 input split
    pack_kernel<<<(256 * QK + 255) / 256, 256>>>(Wq1, bq1, Wk1, bk1, Wv1, bv1, Ws1, bs1,
                                                 We1, Whi1, Wlo1, bp1, Wqe1, bqe1);
    pack_kernel<<<(256 * QK + 255) / 256, 256>>>(Wq2, bq2, Wk2, bk2, Wv2, bv2, Ws2, bs2,
                                                 We2, Whi2, Wlo2, bp2, Wqe2, bqe2);
    split_kernel<<<(NN * 256 + 255) / 256, 256>>>(x);

    // launch 3: layer-1 GEMM (ncu-captured slot)
    float* qkvs; cudaGetSymbolAddress((void**)&qkvs, g_qkvs);
    float* qwe;  cudaGetSymbolAddress((void**)&qwe, g_qwe);
    {
        dim3 gg(QK / 128, (NN + 127) / 128);
        gemm_mma<<<gg, 256>>>(Whi1, Wlo1, bp1, qkvs);
    }
    qwe_kernel<<<(NN * 32 + 255) / 256, 256>>>(x, Wqe1, bqe1);

    // CSR build (needed only by agg)
    detect_kernel<<<1, 32>>>(ei);
    convert_kernel<<<(2 * EE + 255) / 256, 256>>>(ei);
    zero_cnt<<<(NN + 255) / 256, 256>>>();
    count_kernel<<<(EE + 255) / 256, 256>>>();
    scan_kernel<<<1, 1024>>>();
    scatter_kernel<<<(EE + 255) / 256, 256>>>(ew);

    // layer 1 tail
    agg_kernel<<<(NN * 8 * 32 + 255) / 256, 256>>>(qwe);
    finalize<<<(NN * 32 + 127) / 128, 128>>>(Wb1, We1, h1, 1);

    // layers 2, 3
    run_layer(h1, Whi2, Wlo2, bp2, Wqe2, bqe2, We2, Wb2, h2, 1);
    run_layer(h2, Whi2, Wlo2, bp2, Wqe2, bqe2, We2, Wb2, (float*)d_out, 0);
}